// round 2
// baseline (speedup 1.0000x reference)
#include <cuda_runtime.h>

#define NCLS 19
#define CH   32
#define IN_H 128
#define IN_W 128
#define OUT_H 512
#define OUT_W 512
#define NB   4

// Device-global scratch (no allocations allowed in kernel_launch).
__device__ float g_T[(size_t)NB * IN_H * IN_W * CH];   // transposed embedding (N,H,W,C)
__device__ float g_S1[NB * NCLS * CH];                  // per (n,k,c) sum of values
__device__ float g_S2[NB * NCLS * CH];                  // per (n,k,c) sum of squares
__device__ int   g_cnt[NB * NCLS];                      // per (n,k) pixel count

// -------------------------------------------------------------------------
__global__ void init_kernel() {
    int i = blockIdx.x * blockDim.x + threadIdx.x;
    if (i < NB * NCLS * CH) { g_S1[i] = 0.f; g_S2[i] = 0.f; }
    if (i < NB * NCLS) g_cnt[i] = 0;
}

// (N,C,H,W) -> (N,H,W,C) tiled transpose; coalesced read and write.
__global__ void transpose_kernel(const float* __restrict__ in) {
    __shared__ float tile[32][33];
    int n  = blockIdx.z;           // 4
    int y  = blockIdx.y;           // 128
    int xb = blockIdx.x * 32;      // 4 tiles of 32 along W
    int tx = threadIdx.x;          // 32
    int ty = threadIdx.y;          // 32 (channel on read)
    // read: channel ty, x = xb+tx (coalesced in x)
    tile[ty][tx] = in[((((size_t)n * CH + ty) * IN_H + y) * IN_W) + xb + tx];
    __syncthreads();
    // write: x = xb+ty, channel tx (coalesced in c)
    g_T[((((size_t)n * IN_H + y) * IN_W) + xb + ty) * CH + tx] = tile[tx][ty];
}

// -------------------------------------------------------------------------
// Main pass: warp = one output row (y), lane = channel.
// Per-warp private smem bins -> no atomics, conflict-free.
__global__ void __launch_bounds__(256) main_kernel(const int* __restrict__ label) {
    __shared__ float s1[8][NCLS * CH];
    __shared__ float s2[8][NCLS * CH];
    __shared__ int   scnt[8][NCLS];

    const int tid  = threadIdx.x;
    const int w    = tid >> 5;
    const int lane = tid & 31;
    const int n    = blockIdx.x >> 6;        // 4 batches
    const int rb   = blockIdx.x & 63;        // 64 row-blocks
    const int y    = rb * 8 + w;             // warp's output row

    // zero shared bins
    for (int i = tid; i < 8 * NCLS * CH; i += 256) {
        (&s1[0][0])[i] = 0.f;
        (&s2[0][0])[i] = 0.f;
    }
    for (int i = tid; i < 8 * NCLS; i += 256) (&scnt[0][0])[i] = 0;
    __syncthreads();

    // y interpolation params (scale exactly 4, half-pixel sampling)
    const int   y0  = ((y + 2) >> 2) - 1;
    const float fy  = 0.125f + 0.25f * (float)((y + 2) & 3);
    const int   y0c = y0 < 0 ? 0 : y0;
    const int   y1c = (y0 + 1) > (IN_H - 1) ? (IN_H - 1) : (y0 + 1);

    const float* __restrict__ rowA = g_T + ((size_t)(n * IN_H + y0c) * IN_W) * CH + lane;
    const float* __restrict__ rowB = g_T + ((size_t)(n * IN_H + y1c) * IN_W) * CH + lane;
    const int*   __restrict__ labrow = label + ((size_t)(n * OUT_H + y) * OUT_W);

    float* __restrict__ ms1 = s1[w];
    float* __restrict__ ms2 = s2[w];
    int*   __restrict__ mc  = scnt[w];

    // y-lerped fetch of one input column
    auto loady = [&](int col) -> float {
        float a = rowA[col * CH];
        float b = rowB[col * CH];
        return fmaf(fy, b - a, a);
    };
    auto process = [&](int x, float v) {
        int k = labrow[x];                   // class id 0..18 (int32)
        k = k < 0 ? 0 : (k > NCLS - 1 ? NCLS - 1 : k);  // defensive clamp
        int idx = k * CH + lane;
        ms1[idx] += v;
        ms2[idx] = fmaf(v, v, ms2[idx]);
        if (lane == 0) mc[k]++;
    };

    float yv1 = loady(0);
    float yv0 = yv1;
    // g = -1 (left clamp): 2 pixels, d = 0
    process(0, yv0);
    process(1, yv0);
    int x = 2;
    #pragma unroll 4
    for (int g = 0; g < 127; ++g) {
        yv0 = yv1;
        yv1 = loady(g + 1);
        float d = yv1 - yv0;
        process(x + 0, fmaf(0.125f, d, yv0));
        process(x + 1, fmaf(0.375f, d, yv0));
        process(x + 2, fmaf(0.625f, d, yv0));
        process(x + 3, fmaf(0.875f, d, yv0));
        x += 4;
    }
    // g = 127 (right clamp): 2 pixels, d = 0
    yv0 = yv1;
    process(510, yv0);
    process(511, yv0);

    __syncthreads();

    // reduce 8 warp copies -> global atomics
    for (int i = tid; i < NCLS * CH; i += 256) {
        float a = 0.f, b = 0.f;
        #pragma unroll
        for (int ww = 0; ww < 8; ++ww) { a += s1[ww][i]; b += s2[ww][i]; }
        atomicAdd(&g_S1[n * NCLS * CH + i], a);
        atomicAdd(&g_S2[n * NCLS * CH + i], b);
    }
    if (tid < NCLS) {
        int cs = 0;
        #pragma unroll
        for (int ww = 0; ww < 8; ++ww) cs += scnt[ww][tid];
        atomicAdd(&g_cnt[n * NCLS + tid], cs);
    }
}

// -------------------------------------------------------------------------
// Epilogue: one block per batch, warp = class (19 warps = 608 threads).
__global__ void __launch_bounds__(608) epilogue_kernel(float* __restrict__ out) {
    const int n    = blockIdx.x;
    const int tid  = threadIdx.x;
    const int wk   = tid >> 5;   // class id (0..18)
    const int lane = tid & 31;   // channel

    __shared__ float mu[NCLS][CH];
    __shared__ float cntf[NCLS];
    __shared__ float intra[NCLS];
    __shared__ float interAcc;
    __shared__ float nfg_s, l2i_s;

    if (tid < NCLS) cntf[tid] = (float)g_cnt[n * NCLS + tid];
    if (tid == 0) interAcc = 0.f;
    __syncthreads();

    // per-class mean + intra term (algebraic expansion)
    {
        float cn  = cntf[wk];
        float s1  = g_S1[n * NCLS * CH + wk * CH + lane];
        float s2  = g_S2[n * NCLS * CH + wk * CH + lane];
        float m   = s1 / (cn + 1.0f);
        mu[wk][lane] = m;
        float dot = m * s1;
        float m2  = m * m;
        #pragma unroll
        for (int off = 16; off; off >>= 1) {
            s2  += __shfl_xor_sync(0xffffffff, s2,  off);
            dot += __shfl_xor_sync(0xffffffff, dot, off);
            m2  += __shfl_xor_sync(0xffffffff, m2,  off);
        }
        if (lane == 0)
            intra[wk] = (s2 - 2.f * dot + cn * m2) / ((float)CH * (cn + 1.0f));
    }
    __syncthreads();

    if (tid == 0) {
        float nfg = 0.f, li = 0.f;
        for (int k = 1; k < NCLS; ++k)
            if (cntf[k] > 0.f) { nfg += 1.f; li += intra[k]; }
        nfg_s = nfg;
        l2i_s = li / nfg;
    }
    __syncthreads();

    // inter: masked pairwise mean-squared distances between class means
    float acc = 0.f;
    for (int p = wk; p < NCLS * NCLS; p += NCLS) {
        int j = p / NCLS, k = p % NCLS;
        if (j >= 1 && k >= 1 && cntf[j] > 0.f && cntf[k] > 0.f) {
            float d = mu[j][lane] - mu[k][lane];
            acc = fmaf(d, d, acc);
        }
    }
    #pragma unroll
    for (int off = 16; off; off >>= 1)
        acc += __shfl_xor_sync(0xffffffff, acc, off);
    if (lane == 0) atomicAdd(&interAcc, acc / (float)CH);
    __syncthreads();

    if (tid == 0) out[n] = l2i_s - interAcc / (nfg_s * nfg_s);
}

// -------------------------------------------------------------------------
extern "C" void kernel_launch(void* const* d_in, const int* in_sizes, int n_in,
                              void* d_out, int out_size) {
    const float* emb   = (const float*)d_in[0];   // (4,32,128,128) f32
    const int*   label = (const int*)d_in[1];     // (4,512,512) int32 (JAX x64 off)
    float*       out   = (float*)d_out;           // (4,) f32

    init_kernel<<<(NB * NCLS * CH + 255) / 256, 256>>>();
    transpose_kernel<<<dim3(IN_W / 32, IN_H, NB), dim3(32, 32)>>>(emb);
    main_kernel<<<NB * 64, 256>>>(label);
    epilogue_kernel<<<NB, 608>>>(out);
}

// round 3
// speedup vs baseline: 1.0315x; 1.0315x over previous
#include <cuda_runtime.h>

#define NCLS 19
#define CH   32
#define IN_H 128
#define IN_W 128
#define OUT_H 512
#define OUT_W 512
#define NB   4
#define HB   16   // histogram blocks per batch

// Device-global scratch (no allocations allowed in kernel_launch).
__device__ float    g_T[(size_t)NB * IN_H * IN_W * CH];  // transposed embedding (N,H,W,C)
__device__ float    g_S1[NB * NCLS * CH];                // per (n,k,c) sum
__device__ float    g_S2[NB * NCLS * CH];                // per (n,k,c) sum of squares
__device__ int      g_hist[NB][HB][NCLS];                // partial label histograms
__device__ unsigned g_done;

// ---------------------------------------------------------------------------
// Prep: (N,C,H,W)->(N,H,W,C) transpose + zero accumulators + label histogram.
__global__ void __launch_bounds__(1024) prep_kernel(const float* __restrict__ in,
                                                    const int* __restrict__ label) {
    __shared__ float tile[32][33];
    __shared__ int   whist[32][NCLS];

    const int n  = blockIdx.z;          // 4
    const int y  = blockIdx.y;          // 128
    const int xb = blockIdx.x * 32;     // 4 tiles along W
    const int tx = threadIdx.x;
    const int ty = threadIdx.y;
    const int tid = ty * 32 + tx;

    // transpose: read channel ty, x = xb+tx (coalesced)
    tile[ty][tx] = in[((((size_t)n * CH + ty) * IN_H + y) * IN_W) + xb + tx];

    // one block zeroes the global accumulators + done flag
    if (blockIdx.x == 3 && y == 127 && n == 3) {
        for (int i = tid; i < NB * NCLS * CH; i += 1024) { g_S1[i] = 0.f; g_S2[i] = 0.f; }
        if (tid == 0) g_done = 0u;
    }

    // HB blocks per batch build the label histogram (match_any, no atomics)
    if (blockIdx.x == 0 && y < HB) {
        const int w    = tid >> 5;
        const int lane = tid & 31;
        for (int i = lane; i < NCLS; i += 32) whist[w][i] = 0;
        __syncwarp();
        const int4* lp = (const int4*)(label + (size_t)n * OUT_H * OUT_W
                                             + (size_t)y * (OUT_H * OUT_W / HB));
        #pragma unroll
        for (int r = 0; r < 4; ++r) {
            int4 L = lp[r * 1024 + tid];           // coalesced
            int ks[4] = {L.x, L.y, L.z, L.w};
            #pragma unroll
            for (int j = 0; j < 4; ++j) {
                int k = (int)min((unsigned)ks[j], (unsigned)(NCLS - 1));
                unsigned m  = __match_any_sync(0xffffffffu, k);
                int leader  = __ffs(m) - 1;
                if (lane == leader) whist[w][k] += __popc(m);
            }
        }
        __syncthreads();   // block-uniform branch: legal
        if (tid < NCLS) {
            int c = 0;
            #pragma unroll
            for (int ww = 0; ww < 32; ++ww) c += whist[ww][tid];
            g_hist[n][y][tid] = c;
        }
    }

    __syncthreads();
    // write: x = xb+ty, channel tx (coalesced in c)
    g_T[((((size_t)n * IN_H + y) * IN_W) + xb + ty) * CH + tx] = tile[tx][ty];
}

// ---------------------------------------------------------------------------
// Main pass: warp = one output row, lane = channel. Per-warp float2 bins.
// Last CTA computes the full epilogue in-place.
__global__ void __launch_bounds__(256) main_kernel(const int* __restrict__ label,
                                                   float* __restrict__ out) {
    __shared__ __align__(16) unsigned char raw[8 * NCLS * CH * 8];  // 38912 B
    float2 (*s)[NCLS * CH] = reinterpret_cast<float2 (*)[NCLS * CH]>(raw);
    __shared__ unsigned s_last;

    const int tid  = threadIdx.x;
    const int w    = tid >> 5;
    const int lane = tid & 31;
    const int n    = blockIdx.x >> 6;   // 4 batches
    const int rb   = blockIdx.x & 63;   // 64 row-blocks
    const int y    = rb * 8 + w;        // warp's output row

    for (int i = tid; i < 8 * NCLS * CH; i += 256)
        ((float2*)raw)[i] = make_float2(0.f, 0.f);
    __syncthreads();

    // y interpolation (scale exactly 4, half-pixel sampling)
    const int   y0  = ((y + 2) >> 2) - 1;
    const float fy  = 0.125f + 0.25f * (float)((y + 2) & 3);
    const int   y0c = y0 < 0 ? 0 : y0;
    const int   y1c = (y0 + 1) > (IN_H - 1) ? (IN_H - 1) : (y0 + 1);

    const float* __restrict__ rowA = g_T + ((size_t)(n * IN_H + y0c) * IN_W) * CH + lane;
    const float* __restrict__ rowB = g_T + ((size_t)(n * IN_H + y1c) * IN_W) * CH + lane;
    const int4*  __restrict__ lab4 =
        (const int4*)(label + ((size_t)(n * OUT_H + y) * OUT_W));

    float2* __restrict__ sb = s[w];

    auto loady = [&](int c) -> float {
        float a = rowA[c * CH];
        float b = rowB[c * CH];
        return fmaf(fy, b - a, a);
    };
    auto bin = [&](int k, float v) {
        k = (int)min((unsigned)k, (unsigned)(NCLS - 1));
        float2* p = &sb[k * CH + lane];
        float2 o = *p;
        o.x += v;
        o.y = fmaf(v, v, o.y);
        *p = o;
    };

    // aligned 4-pixel groups [4t .. 4t+3]: px0,1 use columns (t-1,t); px2,3 use (t,t+1)
    float yvB = loady(0);
    float yvA = yvB;                       // column -1 clamped
    #pragma unroll 2
    for (int t = 0; t < 127; ++t) {
        float yvC = loady(t + 1);
        int4  L   = lab4[t];
        float d0  = yvB - yvA;
        float d1  = yvC - yvB;
        bin(L.x, fmaf(0.625f, d0, yvA));
        bin(L.y, fmaf(0.875f, d0, yvA));
        bin(L.z, fmaf(0.125f, d1, yvB));
        bin(L.w, fmaf(0.375f, d1, yvB));
        yvA = yvB; yvB = yvC;
    }
    {   // t = 127: column 128 clamps to 127
        int4  L  = lab4[127];
        float d0 = yvB - yvA;
        bin(L.x, fmaf(0.625f, d0, yvA));
        bin(L.y, fmaf(0.875f, d0, yvA));
        bin(L.z, yvB);
        bin(L.w, yvB);
    }
    __syncthreads();

    // reduce 8 warp copies -> global atomics
    for (int i = tid; i < NCLS * CH; i += 256) {
        float a = 0.f, b = 0.f;
        #pragma unroll
        for (int ww = 0; ww < 8; ++ww) { float2 v = s[ww][i]; a += v.x; b += v.y; }
        atomicAdd(&g_S1[n * NCLS * CH + i], a);
        atomicAdd(&g_S2[n * NCLS * CH + i], b);
    }

    __threadfence();
    if (tid == 0) s_last = (atomicAdd(&g_done, 1u) == (unsigned)(gridDim.x - 1));
    __syncthreads();
    if (!s_last) return;

    // ---------------- epilogue (last CTA, reuses smem) ----------------
    struct Epi {
        float cnt[NB][NCLS];
        float mu[NB][NCLS][CH];
        float intra[NB][NCLS];
        float interp[NB][2];
        float nfg[NB];
        float l2i[NB];
    };
    Epi* e = reinterpret_cast<Epi*>(raw);

    if (tid < NB * NCLS) {
        int nn = tid / NCLS, k = tid % NCLS;
        int c = 0;
        #pragma unroll
        for (int h = 0; h < HB; ++h) c += g_hist[nn][h][k];
        e->cnt[nn][k] = (float)c;
    }
    __syncthreads();

    {   // per-class mean + intra (warp pair per batch)
        int nn = w >> 1, sub = w & 1;
        for (int k = sub; k < NCLS; k += 2) {
            float cn = e->cnt[nn][k];
            float s1 = __ldcg(&g_S1[nn * NCLS * CH + k * CH + lane]);
            float s2 = __ldcg(&g_S2[nn * NCLS * CH + k * CH + lane]);
            float m  = s1 / (cn + 1.0f);
            e->mu[nn][k][lane] = m;
            float t2 = s2 + m * fmaf(cn, m, -2.0f * s1);
            #pragma unroll
            for (int o = 16; o; o >>= 1) t2 += __shfl_xor_sync(0xffffffffu, t2, o);
            if (lane == 0) e->intra[nn][k] = t2 / ((float)CH * (cn + 1.0f));
        }
    }
    __syncthreads();

    if (tid < NB) {
        float nf = 0.f, li = 0.f;
        for (int k = 1; k < NCLS; ++k)
            if (e->cnt[tid][k] > 0.f) { nf += 1.f; li += e->intra[tid][k]; }
        e->nfg[tid] = nf;
        e->l2i[tid] = li / nf;
    }
    __syncthreads();

    {   // inter: masked pairwise mean-squared distances
        int nn = w >> 1, sub = w & 1;
        float acc = 0.f;
        for (int p = sub; p < NCLS * NCLS; p += 2) {
            int j = p / NCLS, k = p - j * NCLS;
            if (j >= 1 && k >= 1 && e->cnt[nn][j] > 0.f && e->cnt[nn][k] > 0.f) {
                float d = e->mu[nn][j][lane] - e->mu[nn][k][lane];
                acc = fmaf(d, d, acc);
            }
        }
        #pragma unroll
        for (int o = 16; o; o >>= 1) acc += __shfl_xor_sync(0xffffffffu, acc, o);
        if (lane == 0) e->interp[nn][sub] = acc / (float)CH;
    }
    __syncthreads();

    if (tid < NB) {
        float inter = e->interp[tid][0] + e->interp[tid][1];
        out[tid] = e->l2i[tid] - inter / (e->nfg[tid] * e->nfg[tid]);
    }
}

// ---------------------------------------------------------------------------
extern "C" void kernel_launch(void* const* d_in, const int* in_sizes, int n_in,
                              void* d_out, int out_size) {
    const float* emb   = (const float*)d_in[0];   // (4,32,128,128) f32
    const int*   label = (const int*)d_in[1];     // (4,512,512) int32
    float*       out   = (float*)d_out;           // (4,) f32

    prep_kernel<<<dim3(IN_W / 32, IN_H, NB), dim3(32, 32)>>>(emb, label);
    main_kernel<<<NB * 64, 256>>>(label, out);
}

// round 4
// speedup vs baseline: 1.0894x; 1.0562x over previous
#include <cuda_runtime.h>

#define NCLS 19
#define CH   32
#define IN_H 128
#define IN_W 128
#define OUT_H 512
#define OUT_W 512
#define NB   4
#define HB   16   // histogram blocks per batch
#define GRID_MAIN (NB * 64 * 2)

// Device-global scratch (no allocations allowed in kernel_launch).
__device__ float    g_T[(size_t)NB * IN_H * IN_W * CH];  // transposed embedding (N,H,W,C)
__device__ float    g_S1[NB * NCLS * CH];                // per (n,k,c) sum
__device__ float    g_S2[NB * NCLS * CH];                // per (n,k,c) sum of squares
__device__ int      g_hist[NB][HB][NCLS];                // partial label histograms
__device__ unsigned g_done;

// ---------------------------------------------------------------------------
// Prep: (N,C,H,W)->(N,H,W,C) transpose + zero accumulators + label histogram.
__global__ void __launch_bounds__(1024) prep_kernel(const float* __restrict__ in,
                                                    const int* __restrict__ label) {
    __shared__ float tile[32][33];
    __shared__ int   whist[32][NCLS];

    const int n  = blockIdx.z;          // 4
    const int y  = blockIdx.y;          // 128
    const int xb = blockIdx.x * 32;     // 4 tiles along W
    const int tx = threadIdx.x;
    const int ty = threadIdx.y;
    const int tid = ty * 32 + tx;

    // transpose: read channel ty, x = xb+tx (coalesced)
    tile[ty][tx] = in[((((size_t)n * CH + ty) * IN_H + y) * IN_W) + xb + tx];

    // one block zeroes the global accumulators + done flag
    if (blockIdx.x == 3 && y == 127 && n == 3) {
        for (int i = tid; i < NB * NCLS * CH; i += 1024) { g_S1[i] = 0.f; g_S2[i] = 0.f; }
        if (tid == 0) g_done = 0u;
    }

    // HB blocks per batch build the label histogram (match_any, no atomics)
    if (blockIdx.x == 0 && y < HB) {
        const int w    = tid >> 5;
        const int lane = tid & 31;
        for (int i = lane; i < NCLS; i += 32) whist[w][i] = 0;
        __syncwarp();
        const int4* lp = (const int4*)(label + (size_t)n * OUT_H * OUT_W
                                             + (size_t)y * (OUT_H * OUT_W / HB));
        #pragma unroll
        for (int r = 0; r < 4; ++r) {
            int4 L = lp[r * 1024 + tid];           // coalesced
            int ks[4] = {L.x, L.y, L.z, L.w};
            #pragma unroll
            for (int j = 0; j < 4; ++j) {
                int k = (int)min((unsigned)ks[j], (unsigned)(NCLS - 1));
                unsigned m  = __match_any_sync(0xffffffffu, k);
                int leader  = __ffs(m) - 1;
                if (lane == leader) whist[w][k] += __popc(m);
            }
        }
        __syncthreads();   // block-uniform branch: legal
        if (tid < NCLS) {
            int c = 0;
            #pragma unroll
            for (int ww = 0; ww < 32; ++ww) c += whist[ww][tid];
            g_hist[n][y][tid] = c;
        }
    }

    __syncthreads();
    // write: x = xb+ty, channel tx (coalesced in c)
    g_T[((((size_t)n * IN_H + y) * IN_W) + xb + ty) * CH + tx] = tile[tx][ty];
}

// ---------------------------------------------------------------------------
// Main pass: warp = half an output row (256 px), lane = channel.
// Two independent pixel streams per warp for latency hiding.
__global__ void __launch_bounds__(256) main_kernel(const int* __restrict__ label,
                                                   float* __restrict__ out) {
    __shared__ __align__(16) unsigned char raw[8 * NCLS * CH * 8];  // 38912 B
    float2 (*s)[NCLS * CH] = reinterpret_cast<float2 (*)[NCLS * CH]>(raw);
    __shared__ unsigned s_last;

    const int tid  = threadIdx.x;
    const int w    = tid >> 5;
    const int lane = tid & 31;
    const int bx   = blockIdx.x;
    const int n    = bx >> 7;            // 4 batches
    const int rem  = bx & 127;
    const int rb   = rem >> 1;           // 64 row-blocks
    const int half = rem & 1;            // left / right half of the row
    const int y    = rb * 8 + w;         // warp's output row
    const int t0   = half * 64;          // first 4-px group of this warp

    for (int i = tid; i < 8 * NCLS * CH; i += 256)
        ((float2*)raw)[i] = make_float2(0.f, 0.f);
    __syncthreads();

    // y interpolation (scale exactly 4, half-pixel sampling)
    const int   y0  = ((y + 2) >> 2) - 1;
    const float fy  = 0.125f + 0.25f * (float)((y + 2) & 3);
    const int   y0c = y0 < 0 ? 0 : y0;
    const int   y1c = (y0 + 1) > (IN_H - 1) ? (IN_H - 1) : (y0 + 1);

    const float* __restrict__ rowA = g_T + ((size_t)(n * IN_H + y0c) * IN_W) * CH + lane;
    const float* __restrict__ rowB = g_T + ((size_t)(n * IN_H + y1c) * IN_W) * CH + lane;
    const int4*  __restrict__ lab4 =
        (const int4*)(label + ((size_t)(n * OUT_H + y) * OUT_W));

    float2* __restrict__ sbl = s[w] + lane;

    auto loady = [&](int c) -> float {               // y-lerped, x-clamped column
        c = c < 0 ? 0 : (c > IN_W - 1 ? IN_W - 1 : c);
        float a = rowA[c * CH];
        float b = rowB[c * CH];
        return fmaf(fy, b - a, a);
    };
    auto bin = [&](int k, float v) {
        k = (int)min((unsigned)k, (unsigned)(NCLS - 1));
        float2* p = sbl + k * CH;
        float2 o = *p;
        o.x += v;
        o.y = fmaf(v, v, o.y);
        *p = o;
    };
    // group t: pixels 4t..4t+3 use columns (t-1,t) for px0,1 and (t,t+1) for px2,3.
    auto group = [&](int t, float yvA, float yvB, float yvC) {
        int4  L  = lab4[t];
        float d0 = yvB - yvA;
        float d1 = yvC - yvB;
        bin(L.x, fmaf(0.625f, d0, yvA));
        bin(L.y, fmaf(0.875f, d0, yvA));
        bin(L.z, fmaf(0.125f, d1, yvB));
        bin(L.w, fmaf(0.375f, d1, yvB));
    };

    // two independent streams: groups [t0, t0+32) and [t0+32, t0+64)
    int ta = t0, tb = t0 + 32;
    float aA = loady(ta - 1), aB = loady(ta);
    float bA = loady(tb - 1), bB = loady(tb);
    #pragma unroll 2
    for (int i = 0; i < 32; ++i) {
        float aC = loady(ta + 1);
        float bC = loady(tb + 1);
        group(ta, aA, aB, aC);
        group(tb, bA, bB, bC);
        aA = aB; aB = aC;
        bA = bB; bB = bC;
        ++ta; ++tb;
    }
    __syncthreads();

    // reduce 8 warp copies -> global atomics
    for (int i = tid; i < NCLS * CH; i += 256) {
        float a = 0.f, b = 0.f;
        #pragma unroll
        for (int ww = 0; ww < 8; ++ww) { float2 v = s[ww][i]; a += v.x; b += v.y; }
        atomicAdd(&g_S1[n * NCLS * CH + i], a);
        atomicAdd(&g_S2[n * NCLS * CH + i], b);
    }

    __threadfence();
    if (tid == 0) s_last = (atomicAdd(&g_done, 1u) == (unsigned)(gridDim.x - 1));
    __syncthreads();
    if (!s_last) return;

    // ---------------- epilogue (last CTA, reuses smem) ----------------
    struct Epi {
        float cnt[NB][NCLS];
        float mu[NB][NCLS][CH];
        float intra[NB][NCLS];
        float interp[NB][2];
        float nfg[NB];
        float l2i[NB];
    };
    Epi* e = reinterpret_cast<Epi*>(raw);

    if (tid < NB * NCLS) {
        int nn = tid / NCLS, k = tid % NCLS;
        int c = 0;
        #pragma unroll
        for (int h = 0; h < HB; ++h) c += g_hist[nn][h][k];
        e->cnt[nn][k] = (float)c;
    }
    __syncthreads();

    {   // per-class mean + intra (warp pair per batch)
        int nn = w >> 1, sub = w & 1;
        for (int k = sub; k < NCLS; k += 2) {
            float cn = e->cnt[nn][k];
            float s1 = __ldcg(&g_S1[nn * NCLS * CH + k * CH + lane]);
            float s2 = __ldcg(&g_S2[nn * NCLS * CH + k * CH + lane]);
            float m  = s1 / (cn + 1.0f);
            e->mu[nn][k][lane] = m;
            float t2 = s2 + m * fmaf(cn, m, -2.0f * s1);
            #pragma unroll
            for (int o = 16; o; o >>= 1) t2 += __shfl_xor_sync(0xffffffffu, t2, o);
            if (lane == 0) e->intra[nn][k] = t2 / ((float)CH * (cn + 1.0f));
        }
    }
    __syncthreads();

    if (tid < NB) {
        float nf = 0.f, li = 0.f;
        for (int k = 1; k < NCLS; ++k)
            if (e->cnt[tid][k] > 0.f) { nf += 1.f; li += e->intra[tid][k]; }
        e->nfg[tid] = nf;
        e->l2i[tid] = li / nf;
    }
    __syncthreads();

    {   // inter: masked pairwise mean-squared distances
        int nn = w >> 1, sub = w & 1;
        float acc = 0.f;
        for (int p = sub; p < NCLS * NCLS; p += 2) {
            int j = p / NCLS, k = p - j * NCLS;
            if (j >= 1 && k >= 1 && e->cnt[nn][j] > 0.f && e->cnt[nn][k] > 0.f) {
                float d = e->mu[nn][j][lane] - e->mu[nn][k][lane];
                acc = fmaf(d, d, acc);
            }
        }
        #pragma unroll
        for (int o = 16; o; o >>= 1) acc += __shfl_xor_sync(0xffffffffu, acc, o);
        if (lane == 0) e->interp[nn][sub] = acc / (float)CH;
    }
    __syncthreads();

    if (tid < NB) {
        float inter = e->interp[tid][0] + e->interp[tid][1];
        out[tid] = e->l2i[tid] - inter / (e->nfg[tid] * e->nfg[tid]);
    }
}

// ---------------------------------------------------------------------------
extern "C" void kernel_launch(void* const* d_in, const int* in_sizes, int n_in,
                              void* d_out, int out_size) {
    const float* emb   = (const float*)d_in[0];   // (4,32,128,128) f32
    const int*   label = (const int*)d_in[1];     // (4,512,512) int32
    float*       out   = (float*)d_out;           // (4,) f32

    prep_kernel<<<dim3(IN_W / 32, IN_H, NB), dim3(32, 32)>>>(emb, label);
    main_kernel<<<GRID_MAIN, 256>>>(label, out);
}